// round 15
// baseline (speedup 1.0000x reference)
#include <cuda_runtime.h>
#include <math.h>

#define B_   8
#define C_   64
#define H_   256
#define W_   256
#define LD_  8
#define MEM_ 128
// reduce: 128-row chunks (R13 measured form)
#define HCH_R 128
#define NQR_  (H_ / HCH_R)        // 2
#define RBLK_ (B_ * C_ * NQR_)    // 1024
#define CQ_   (C_ * NQR_)         // 128
#define TP_   (CQ_ + 1)           // 129
// apply: 64-row chunks (R12/R13 measured form)
#define HCH_A 64
#define NQA_  (H_ / HCH_A)        // 4
#define ABLK_ (B_ * C_ * NQA_)    // 2048

// Scratch (allocation-free per harness rules)
__device__ float g_part[RBLK_ * W_];     // partials [b][c*2+q][w] (1 MB)
__device__ float g_gateT[B_ * C_ * W_];  // gate*mu, [bc][w] (0.5 MB)
__device__ unsigned g_gatec[B_];         // gate arrivals per batch (32 each)
__device__ unsigned g_done;              // last-block-out reset

// ---------------------------------------------------------------------------
// Kernel 1: partial sum over a 128-row h-chunk of one (b,c) plane.
// (Exact R13 form: 23.4us measured, 74.7% DRAM.)
// ---------------------------------------------------------------------------
__global__ __launch_bounds__(256) void reduce_h_partial_kernel(const float* __restrict__ x) {
    const int bcq = blockIdx.x;           // = (b*C+c)*2 + q
    const int t  = threadIdx.x;
    const int w4 = t & 63;
    const int hs = t >> 6;

    const float4* __restrict__ xp =
        (const float4*)(x + (size_t)(bcq >> 1) * (H_ * W_) +
                        (size_t)(bcq & 1) * HCH_R * W_);

    float4 s0 = make_float4(0.f, 0.f, 0.f, 0.f);
    float4 s1 = make_float4(0.f, 0.f, 0.f, 0.f);

#pragma unroll
    for (int grp = 0; grp < 4; ++grp) {
        float4 v[8];
#pragma unroll
        for (int k = 0; k < 8; ++k)
            v[k] = xp[(size_t)(hs + 4 * (grp * 8 + k)) * (W_ / 4) + w4];
#pragma unroll
        for (int k = 0; k < 8; ++k) {
            if (k & 1) { s1.x += v[k].x; s1.y += v[k].y; s1.z += v[k].z; s1.w += v[k].w; }
            else       { s0.x += v[k].x; s0.y += v[k].y; s0.z += v[k].z; s0.w += v[k].w; }
        }
    }
    float4 s = make_float4(s0.x + s1.x, s0.y + s1.y, s0.z + s1.z, s0.w + s1.w);

    __shared__ float4 red[256];
    red[t] = s;
    __syncthreads();
    if (hs == 0) {
        float4 a = red[t], b1 = red[t + 64], c1 = red[t + 128], d = red[t + 192];
        a.x += b1.x + c1.x + d.x;
        a.y += b1.y + c1.y + d.y;
        a.z += b1.z + c1.z + d.z;
        a.w += b1.w + c1.w + d.w;
        __stcs(&((float4*)g_part)[(size_t)bcq * (W_ / 4) + w4], a);
    }
}

// ---------------------------------------------------------------------------
// Kernel 2 (fused gate+apply): blocks 0..255 FIRST compute their gate slice
// (no dependency inside this kernel -> no deadlock), signal per-batch
// counters; every block then spin-waits for its batch's 32 gate signals
// (overlapped with ramp) and streams its apply chunk (R12 batch-8 body).
// ---------------------------------------------------------------------------
__global__ __launch_bounds__(256) void gate_apply_kernel(
    const float* __restrict__ x, float* __restrict__ out,
    const float* __restrict__ w_sub, const float* __restrict__ b_sub,
    const float* __restrict__ w_up,  const float* __restrict__ b_up,
    const float* __restrict__ mb,    const float* __restrict__ mu)
{
    const int tid  = threadIdx.x;
    const int w4   = tid & 63;
    const int hs   = tid >> 6;
    const int lane = tid & 31;

    // ---------------- gate phase: blocks 0..255 ----------------
    if (blockIdx.x < 256) {
        __shared__ float s_wsub[C_ * LD_];
        __shared__ float s_mb[LD_ * MEM_];
        __shared__ float s_wup[LD_ * C_];
        __shared__ float s_bsub[LD_];
        __shared__ float s_bup[C_];
        __shared__ float tile[8 * TP_];

        const int b  = blockIdx.x >> 5;
        const int w8 = (blockIdx.x & 31) * 8;

        for (int i = tid; i < C_ * LD_;   i += 256) s_wsub[i] = w_sub[i];
        for (int i = tid; i < LD_ * MEM_; i += 256) s_mb[i]   = mb[i];
        for (int i = tid; i < LD_ * C_;   i += 256) s_wup[i]  = w_up[i];
        if (tid < LD_) s_bsub[tid] = b_sub[tid];
        if (tid < C_)  s_bup[tid]  = b_up[tid];

        // stage + transpose the 128(cq) x 8(w) tile
#pragma unroll
        for (int it = 0; it < 4; ++it) {
            const int cq = (tid >> 3) + 32 * it;
            const int wl = tid & 7;
            tile[wl * TP_ + cq] = g_part[((size_t)b * CQ_ + cq) * W_ + w8 + wl];
        }
        __syncthreads();

        const float muv   = mu[0];
        const float inv_h = 1.0f / H_;
        const float scale = rsqrtf((float)LD_);
        const int wp = tid >> 5;
        const int w  = w8 + wp;
        const float* tr = tile + wp * TP_;

        const float yA = (tr[lane * 2] + tr[lane * 2 + 1]) * inv_h;
        const float yB = (tr[(lane + 32) * 2] + tr[(lane + 32) * 2 + 1]) * inv_h;

        float low[LD_];
#pragma unroll
        for (int j = 0; j < LD_; ++j) {
            float p = fmaf(yA, s_wsub[lane * LD_ + j],
                           yB * s_wsub[(lane + 32) * LD_ + j]);
#pragma unroll
            for (int off = 16; off > 0; off >>= 1)
                p += __shfl_xor_sync(0xffffffffu, p, off);
            low[j] = p + s_bsub[j];
        }

        float f1[4];
#pragma unroll
        for (int k = 0; k < 4; ++k) {
            const int m = lane + 32 * k;
            float acc = 0.f;
#pragma unroll
            for (int j = 0; j < LD_; ++j)
                acc = fmaf(low[j], s_mb[j * MEM_ + m], acc);
            f1[k] = acc * scale;
        }

        float mx = fmaxf(fmaxf(f1[0], f1[1]), fmaxf(f1[2], f1[3]));
#pragma unroll
        for (int off = 16; off > 0; off >>= 1)
            mx = fmaxf(mx, __shfl_xor_sync(0xffffffffu, mx, off));
        float e[4], sum = 0.f;
#pragma unroll
        for (int k = 0; k < 4; ++k) { e[k] = expf(f1[k] - mx); sum += e[k]; }
#pragma unroll
        for (int off = 16; off > 0; off >>= 1)
            sum += __shfl_xor_sync(0xffffffffu, sum, off);
        const float inv = 1.0f / sum;

        float y1[LD_];
#pragma unroll
        for (int j = 0; j < LD_; ++j) {
            float acc = 0.f;
#pragma unroll
            for (int k = 0; k < 4; ++k)
                acc = fmaf(e[k] * inv, s_mb[j * MEM_ + lane + 32 * k], acc);
#pragma unroll
            for (int off = 16; off > 0; off >>= 1)
                acc += __shfl_xor_sync(0xffffffffu, acc, off);
            y1[j] = acc;
        }

#pragma unroll
        for (int k = 0; k < 2; ++k) {
            const int c = lane + 32 * k;
            float acc = s_bup[c];
#pragma unroll
            for (int j = 0; j < LD_; ++j)
                acc = fmaf(y1[j], s_wup[j * C_ + c], acc);
            const float g = 1.0f / (1.0f + expf(-acc));
            g_gateT[(size_t)(b * C_ + c) * W_ + w] = g * muv;
        }

        __threadfence();
        __syncthreads();
        if (tid == 0) atomicAdd(&g_gatec[b], 1u);
    }

    // ---------------- apply phase: all 2048 blocks ----------------
    {
        const int bcq   = (ABLK_ - 1) - blockIdx.x;   // reverse order
        const int bc    = bcq >> 2;
        const int q     = bcq & (NQA_ - 1);
        const int batch = bc / C_;

        if (tid == 0) {
            while (((volatile unsigned*)g_gatec)[batch] < 32u) __nanosleep(50);
        }
        __syncthreads();
        __threadfence();

        const float4 gv = __ldg(&((const float4*)(g_gateT + (size_t)bc * W_))[w4]);

        const size_t base = (size_t)bc * (H_ * W_) + (size_t)q * HCH_A * W_;
        const float4* __restrict__ xp = (const float4*)(x + base);
        float4*       __restrict__ op = (float4*)(out + base);

#pragma unroll
        for (int half = 0; half < 2; ++half) {
            float4 v[8];
#pragma unroll
            for (int k = 0; k < 8; ++k)
                v[k] = __ldcs(&xp[(size_t)(hs + 4 * (half * 8 + k)) * (W_ / 4) + w4]);
#pragma unroll
            for (int k = 0; k < 8; ++k) {
                v[k].x *= gv.x; v[k].y *= gv.y; v[k].z *= gv.z; v[k].w *= gv.w;
                __stcs(&op[(size_t)(hs + 4 * (half * 8 + k)) * (W_ / 4) + w4], v[k]);
            }
        }
    }

    // ---------------- last-block-out: reset counters for replay ----------------
    __syncthreads();
    if (tid == 0) {
        __threadfence();
        const unsigned d = atomicAdd(&g_done, 1u);
        if (d == (unsigned)(ABLK_ - 1)) {
#pragma unroll
            for (int i = 0; i < B_; ++i) g_gatec[i] = 0u;
            __threadfence();
            g_done = 0u;
        }
    }
}

extern "C" void kernel_launch(void* const* d_in, const int* in_sizes, int n_in,
                              void* d_out, int out_size) {
    const float* x     = (const float*)d_in[0];
    const float* w_sub = (const float*)d_in[1];
    const float* b_sub = (const float*)d_in[2];
    const float* w_up  = (const float*)d_in[3];
    const float* b_up  = (const float*)d_in[4];
    const float* mb    = (const float*)d_in[5];
    const float* mu    = (const float*)d_in[6];
    float* out = (float*)d_out;

    reduce_h_partial_kernel<<<RBLK_, 256>>>(x);
    gate_apply_kernel<<<ABLK_, 256>>>(x, out, w_sub, b_sub, w_up, b_up, mb, mu);
}

// round 16
// speedup vs baseline: 1.0774x; 1.0774x over previous
#include <cuda_runtime.h>
#include <math.h>

#define B_   8
#define C_   64
#define H_   256
#define W_   256
#define LD_  8
#define MEM_ 128
// reduce: 128-row chunks (R13 measured form)
#define HCH_R 128
#define NQR_  (H_ / HCH_R)        // 2
#define RBLK_ (B_ * C_ * NQR_)    // 1024
#define CQ_   (C_ * NQR_)         // 128
#define TP_   (CQ_ + 1)           // 129
// apply: 64-row chunks (R12/R13 measured form)
#define HCH_A 64
#define NQA_  (H_ / HCH_A)        // 4
#define ABLK_ (B_ * C_ * NQA_)    // 2048

// Scratch (allocation-free per harness rules)
__device__ float g_part[RBLK_ * W_];     // partials [b][c*2+q][w] (1 MB)
__device__ float g_gateT[B_ * C_ * W_];  // gate*mu, [bc][w] (0.5 MB)

// ---------------------------------------------------------------------------
// Kernel 1: partial sum over a 128-row h-chunk of one (b,c) plane.
// (Exact R13 body + early PDL trigger after the load loop.)
// ---------------------------------------------------------------------------
__global__ __launch_bounds__(256) void reduce_h_partial_kernel(const float* __restrict__ x) {
    const int bcq = blockIdx.x;           // = (b*C+c)*2 + q
    const int t  = threadIdx.x;
    const int w4 = t & 63;
    const int hs = t >> 6;

    const float4* __restrict__ xp =
        (const float4*)(x + (size_t)(bcq >> 1) * (H_ * W_) +
                        (size_t)(bcq & 1) * HCH_R * W_);

    float4 s0 = make_float4(0.f, 0.f, 0.f, 0.f);
    float4 s1 = make_float4(0.f, 0.f, 0.f, 0.f);

#pragma unroll
    for (int grp = 0; grp < 4; ++grp) {
        float4 v[8];
#pragma unroll
        for (int k = 0; k < 8; ++k)
            v[k] = xp[(size_t)(hs + 4 * (grp * 8 + k)) * (W_ / 4) + w4];
#pragma unroll
        for (int k = 0; k < 8; ++k) {
            if (k & 1) { s1.x += v[k].x; s1.y += v[k].y; s1.z += v[k].z; s1.w += v[k].w; }
            else       { s0.x += v[k].x; s0.y += v[k].y; s0.z += v[k].z; s0.w += v[k].w; }
        }
    }

    // PDL: allow the gate kernel to launch + run its weight prologue while
    // our tail blocks finish. Data visibility is enforced by the consumer's
    // cudaGridDependencySynchronize(), not by this trigger.
    cudaTriggerProgrammaticLaunchCompletion();

    float4 s = make_float4(s0.x + s1.x, s0.y + s1.y, s0.z + s1.z, s0.w + s1.w);

    __shared__ float4 red[256];
    red[t] = s;
    __syncthreads();
    if (hs == 0) {
        float4 a = red[t], b1 = red[t + 64], c1 = red[t + 128], d = red[t + 192];
        a.x += b1.x + c1.x + d.x;
        a.y += b1.y + c1.y + d.y;
        a.z += b1.z + c1.z + d.z;
        a.w += b1.w + c1.w + d.w;
        __stcs(&((float4*)g_part)[(size_t)bcq * (W_ / 4) + w4], a);
    }
}

// ---------------------------------------------------------------------------
// Kernel 2: gating MLP + memory-bank attention. 256 blocks; block = (b, 8 w).
// (Exact R13 body; weight prologue runs BEFORE the grid-dependency sync so it
// overlaps the reduce tail under PDL.)
// ---------------------------------------------------------------------------
__global__ __launch_bounds__(256) void gate_kernel(
    const float* __restrict__ w_sub, const float* __restrict__ b_sub,
    const float* __restrict__ w_up,  const float* __restrict__ b_up,
    const float* __restrict__ mb,    const float* __restrict__ mu)
{
    __shared__ float s_wsub[C_ * LD_];
    __shared__ float s_mb[LD_ * MEM_];
    __shared__ float s_wup[LD_ * C_];
    __shared__ float s_bsub[LD_];
    __shared__ float s_bup[C_];
    __shared__ float tile[8 * TP_];

    const int tid = threadIdx.x;
    // Prologue: independent of reduce output — overlaps reduce tail via PDL.
    for (int i = tid; i < C_ * LD_;   i += 256) s_wsub[i] = w_sub[i];
    for (int i = tid; i < LD_ * MEM_; i += 256) s_mb[i]   = mb[i];
    for (int i = tid; i < LD_ * C_;   i += 256) s_wup[i]  = w_up[i];
    if (tid < LD_) s_bsub[tid] = b_sub[tid];
    if (tid < C_)  s_bup[tid]  = b_up[tid];

    // Wait for ALL of reduce's memory to be visible.
    cudaGridDependencySynchronize();

    const int b  = blockIdx.x >> 5;            // batch
    const int w8 = (blockIdx.x & 31) * 8;      // w slice start

#pragma unroll
    for (int it = 0; it < 4; ++it) {
        const int cq = (tid >> 3) + 32 * it;
        const int wl = tid & 7;
        tile[wl * TP_ + cq] = g_part[((size_t)b * CQ_ + cq) * W_ + w8 + wl];
    }
    __syncthreads();

    const float muv   = mu[0];
    const float inv_h = 1.0f / H_;
    const float scale = rsqrtf((float)LD_);

    const int wp   = tid >> 5;
    const int lane = tid & 31;
    const int w    = w8 + wp;
    const float* tr = tile + wp * TP_;

    const float yA = (tr[lane * 2] + tr[lane * 2 + 1]) * inv_h;
    const float yB = (tr[(lane + 32) * 2] + tr[(lane + 32) * 2 + 1]) * inv_h;

    float low[LD_];
#pragma unroll
    for (int j = 0; j < LD_; ++j) {
        float p = fmaf(yA, s_wsub[lane * LD_ + j],
                       yB * s_wsub[(lane + 32) * LD_ + j]);
#pragma unroll
        for (int off = 16; off > 0; off >>= 1)
            p += __shfl_xor_sync(0xffffffffu, p, off);
        low[j] = p + s_bsub[j];
    }

    float f1[4];
#pragma unroll
    for (int k = 0; k < 4; ++k) {
        const int m = lane + 32 * k;
        float acc = 0.f;
#pragma unroll
        for (int j = 0; j < LD_; ++j)
            acc = fmaf(low[j], s_mb[j * MEM_ + m], acc);
        f1[k] = acc * scale;
    }

    float mx = fmaxf(fmaxf(f1[0], f1[1]), fmaxf(f1[2], f1[3]));
#pragma unroll
    for (int off = 16; off > 0; off >>= 1)
        mx = fmaxf(mx, __shfl_xor_sync(0xffffffffu, mx, off));
    float e[4], sum = 0.f;
#pragma unroll
    for (int k = 0; k < 4; ++k) { e[k] = expf(f1[k] - mx); sum += e[k]; }
#pragma unroll
    for (int off = 16; off > 0; off >>= 1)
        sum += __shfl_xor_sync(0xffffffffu, sum, off);
    const float inv = 1.0f / sum;

    float y1[LD_];
#pragma unroll
    for (int j = 0; j < LD_; ++j) {
        float acc = 0.f;
#pragma unroll
        for (int k = 0; k < 4; ++k)
            acc = fmaf(e[k] * inv, s_mb[j * MEM_ + lane + 32 * k], acc);
#pragma unroll
        for (int off = 16; off > 0; off >>= 1)
            acc += __shfl_xor_sync(0xffffffffu, acc, off);
        y1[j] = acc;
    }

#pragma unroll
    for (int k = 0; k < 2; ++k) {
        const int c = lane + 32 * k;
        float acc = s_bup[c];
#pragma unroll
        for (int j = 0; j < LD_; ++j)
            acc = fmaf(y1[j], s_wup[j * C_ + c], acc);
        const float g = 1.0f / (1.0f + expf(-acc));
        g_gateT[(size_t)(b * C_ + c) * W_ + w] = g * muv;
    }
}

// ---------------------------------------------------------------------------
// Kernel 3: out = x * gate. (Exact R12/R13 body + grid-dependency sync.)
// ---------------------------------------------------------------------------
__global__ __launch_bounds__(256) void apply_gate_kernel(
    const float* __restrict__ x, float* __restrict__ out)
{
    // Launches early under PDL; wait for gate's stores to be visible.
    cudaGridDependencySynchronize();

    const int bcq = (ABLK_ - 1) - blockIdx.x;   // reverse order
    const int bc  = bcq >> 2;
    const int q   = bcq & (NQA_ - 1);

    const int t   = threadIdx.x;
    const int w4  = t & 63;
    const int hs  = t >> 6;

    const float4 gv = __ldg(&((const float4*)(g_gateT + (size_t)bc * W_))[w4]);

    const size_t base = (size_t)bc * (H_ * W_) + (size_t)q * HCH_A * W_;
    const float4* __restrict__ xp = (const float4*)(x + base);
    float4*       __restrict__ op = (float4*)(out + base);

#pragma unroll
    for (int half = 0; half < 2; ++half) {
        float4 v[8];
#pragma unroll
        for (int k = 0; k < 8; ++k)
            v[k] = __ldcs(&xp[(size_t)(hs + 4 * (half * 8 + k)) * (W_ / 4) + w4]);
#pragma unroll
        for (int k = 0; k < 8; ++k) {
            v[k].x *= gv.x; v[k].y *= gv.y; v[k].z *= gv.z; v[k].w *= gv.w;
            __stcs(&op[(size_t)(hs + 4 * (half * 8 + k)) * (W_ / 4) + w4], v[k]);
        }
    }
}

extern "C" void kernel_launch(void* const* d_in, const int* in_sizes, int n_in,
                              void* d_out, int out_size) {
    const float* x     = (const float*)d_in[0];
    const float* w_sub = (const float*)d_in[1];
    const float* b_sub = (const float*)d_in[2];
    const float* w_up  = (const float*)d_in[3];
    const float* b_up  = (const float*)d_in[4];
    const float* mb    = (const float*)d_in[5];
    const float* mu    = (const float*)d_in[6];
    float* out = (float*)d_out;

    // K1: plain launch.
    reduce_h_partial_kernel<<<RBLK_, 256>>>(x);

    // K2, K3: programmatic dependent launches (overlap launch/prologue with
    // the predecessor's tail; device-side GridDependencySynchronize enforces
    // data visibility).
    cudaLaunchAttribute attr[1];
    attr[0].id = cudaLaunchAttributeProgrammaticStreamSerialization;
    attr[0].val.programmaticStreamSerializationAllowed = 1;

    {
        cudaLaunchConfig_t cfg = {};
        cfg.gridDim  = dim3(256, 1, 1);
        cfg.blockDim = dim3(256, 1, 1);
        cfg.attrs    = attr;
        cfg.numAttrs = 1;
        cudaLaunchKernelEx(&cfg, gate_kernel, w_sub, b_sub, w_up, b_up, mb, mu);
    }
    {
        cudaLaunchConfig_t cfg = {};
        cfg.gridDim  = dim3(ABLK_, 1, 1);
        cfg.blockDim = dim3(256, 1, 1);
        cfg.attrs    = attr;
        cfg.numAttrs = 1;
        cudaLaunchKernelEx(&cfg, apply_gate_kernel, x, out);
    }
}

// round 17
// speedup vs baseline: 1.0868x; 1.0087x over previous
#include <cuda_runtime.h>
#include <math.h>

#define B_   8
#define C_   64
#define H_   256
#define W_   256
#define LD_  8
#define MEM_ 128
// reduce: 128-row chunks (R13 measured form)
#define HCH_R 128
#define NQR_  (H_ / HCH_R)        // 2
#define RBLK_ (B_ * C_ * NQR_)    // 1024
#define CQ_   (C_ * NQR_)         // 128
#define TP_   (CQ_ + 1)           // 129
// apply: 64-row chunks (R12/R13 measured form)
#define HCH_A 64
#define NQA_  (H_ / HCH_A)        // 4
#define ABLK_ (B_ * C_ * NQA_)    // 2048

// Scratch (allocation-free per harness rules)
__device__ float g_part[RBLK_ * W_];     // partials [b][c*2+q][w] (1 MB)
__device__ float g_gateT[B_ * C_ * W_];  // gate*mu, [bc][w] (0.5 MB)

// ---------------------------------------------------------------------------
// Kernel 1: partial sum over a 128-row h-chunk of one (b,c) plane.
// Exact R13 body; PDL trigger at the VERY END so secondary kernels launch
// only into the drain window, not the steady-state stream.
// ---------------------------------------------------------------------------
__global__ __launch_bounds__(256) void reduce_h_partial_kernel(const float* __restrict__ x) {
    const int bcq = blockIdx.x;           // = (b*C+c)*2 + q
    const int t  = threadIdx.x;
    const int w4 = t & 63;
    const int hs = t >> 6;

    const float4* __restrict__ xp =
        (const float4*)(x + (size_t)(bcq >> 1) * (H_ * W_) +
                        (size_t)(bcq & 1) * HCH_R * W_);

    float4 s0 = make_float4(0.f, 0.f, 0.f, 0.f);
    float4 s1 = make_float4(0.f, 0.f, 0.f, 0.f);

#pragma unroll
    for (int grp = 0; grp < 4; ++grp) {
        float4 v[8];
#pragma unroll
        for (int k = 0; k < 8; ++k)
            v[k] = xp[(size_t)(hs + 4 * (grp * 8 + k)) * (W_ / 4) + w4];
#pragma unroll
        for (int k = 0; k < 8; ++k) {
            if (k & 1) { s1.x += v[k].x; s1.y += v[k].y; s1.z += v[k].z; s1.w += v[k].w; }
            else       { s0.x += v[k].x; s0.y += v[k].y; s0.z += v[k].z; s0.w += v[k].w; }
        }
    }
    float4 s = make_float4(s0.x + s1.x, s0.y + s1.y, s0.z + s1.z, s0.w + s1.w);

    __shared__ float4 red[256];
    red[t] = s;
    __syncthreads();
    if (hs == 0) {
        float4 a = red[t], b1 = red[t + 64], c1 = red[t + 128], d = red[t + 192];
        a.x += b1.x + c1.x + d.x;
        a.y += b1.y + c1.y + d.y;
        a.z += b1.z + c1.z + d.z;
        a.w += b1.w + c1.w + d.w;
        __stcs(&((float4*)g_part)[(size_t)bcq * (W_ / 4) + w4], a);
    }

    // PDL trigger LAST: secondary kernels begin launching only as this grid
    // drains. Visibility of g_part is enforced by the consumer's
    // cudaGridDependencySynchronize (waits for this grid's completion).
    cudaTriggerProgrammaticLaunchCompletion();
}

// ---------------------------------------------------------------------------
// Kernel 2: gating MLP + memory-bank attention. 256 blocks; block = (b, 8 w).
// Weight prologue runs BEFORE the grid sync (overlaps the reduce drain).
// ---------------------------------------------------------------------------
__global__ __launch_bounds__(256) void gate_kernel(
    const float* __restrict__ w_sub, const float* __restrict__ b_sub,
    const float* __restrict__ w_up,  const float* __restrict__ b_up,
    const float* __restrict__ mb,    const float* __restrict__ mu)
{
    __shared__ float s_wsub[C_ * LD_];
    __shared__ float s_mb[LD_ * MEM_];
    __shared__ float s_wup[LD_ * C_];
    __shared__ float s_bsub[LD_];
    __shared__ float s_bup[C_];
    __shared__ float tile[8 * TP_];

    const int tid = threadIdx.x;
    for (int i = tid; i < C_ * LD_;   i += 256) s_wsub[i] = w_sub[i];
    for (int i = tid; i < LD_ * MEM_; i += 256) s_mb[i]   = mb[i];
    for (int i = tid; i < LD_ * C_;   i += 256) s_wup[i]  = w_up[i];
    if (tid < LD_) s_bsub[tid] = b_sub[tid];
    if (tid < C_)  s_bup[tid]  = b_up[tid];

    cudaGridDependencySynchronize();

    const int b  = blockIdx.x >> 5;            // batch
    const int w8 = (blockIdx.x & 31) * 8;      // w slice start

#pragma unroll
    for (int it = 0; it < 4; ++it) {
        const int cq = (tid >> 3) + 32 * it;
        const int wl = tid & 7;
        tile[wl * TP_ + cq] = g_part[((size_t)b * CQ_ + cq) * W_ + w8 + wl];
    }
    __syncthreads();

    const float muv   = mu[0];
    const float inv_h = 1.0f / H_;
    const float scale = rsqrtf((float)LD_);

    const int wp   = tid >> 5;
    const int lane = tid & 31;
    const int w    = w8 + wp;
    const float* tr = tile + wp * TP_;

    const float yA = (tr[lane * 2] + tr[lane * 2 + 1]) * inv_h;
    const float yB = (tr[(lane + 32) * 2] + tr[(lane + 32) * 2 + 1]) * inv_h;

    float low[LD_];
#pragma unroll
    for (int j = 0; j < LD_; ++j) {
        float p = fmaf(yA, s_wsub[lane * LD_ + j],
                       yB * s_wsub[(lane + 32) * LD_ + j]);
#pragma unroll
        for (int off = 16; off > 0; off >>= 1)
            p += __shfl_xor_sync(0xffffffffu, p, off);
        low[j] = p + s_bsub[j];
    }

    float f1[4];
#pragma unroll
    for (int k = 0; k < 4; ++k) {
        const int m = lane + 32 * k;
        float acc = 0.f;
#pragma unroll
        for (int j = 0; j < LD_; ++j)
            acc = fmaf(low[j], s_mb[j * MEM_ + m], acc);
        f1[k] = acc * scale;
    }

    float mx = fmaxf(fmaxf(f1[0], f1[1]), fmaxf(f1[2], f1[3]));
#pragma unroll
    for (int off = 16; off > 0; off >>= 1)
        mx = fmaxf(mx, __shfl_xor_sync(0xffffffffu, mx, off));
    float e[4], sum = 0.f;
#pragma unroll
    for (int k = 0; k < 4; ++k) { e[k] = expf(f1[k] - mx); sum += e[k]; }
#pragma unroll
    for (int off = 16; off > 0; off >>= 1)
        sum += __shfl_xor_sync(0xffffffffu, sum, off);
    const float inv = 1.0f / sum;

    float y1[LD_];
#pragma unroll
    for (int j = 0; j < LD_; ++j) {
        float acc = 0.f;
#pragma unroll
        for (int k = 0; k < 4; ++k)
            acc = fmaf(e[k] * inv, s_mb[j * MEM_ + lane + 32 * k], acc);
#pragma unroll
        for (int off = 16; off > 0; off >>= 1)
            acc += __shfl_xor_sync(0xffffffffu, acc, off);
        y1[j] = acc;
    }

#pragma unroll
    for (int k = 0; k < 2; ++k) {
        const int c = lane + 32 * k;
        float acc = s_bup[c];
#pragma unroll
        for (int j = 0; j < LD_; ++j)
            acc = fmaf(y1[j], s_wup[j * C_ + c], acc);
        const float g = 1.0f / (1.0f + expf(-acc));
        g_gateT[(size_t)(b * C_ + c) * W_ + w] = g * muv;
    }

    cudaTriggerProgrammaticLaunchCompletion();
}

// ---------------------------------------------------------------------------
// Kernel 3: out = x * gate. (Exact R12/R13 body + grid-dependency sync.)
// ---------------------------------------------------------------------------
__global__ __launch_bounds__(256) void apply_gate_kernel(
    const float* __restrict__ x, float* __restrict__ out)
{
    cudaGridDependencySynchronize();

    const int bcq = (ABLK_ - 1) - blockIdx.x;   // reverse order
    const int bc  = bcq >> 2;
    const int q   = bcq & (NQA_ - 1);

    const int t   = threadIdx.x;
    const int w4  = t & 63;
    const int hs  = t >> 6;

    const float4 gv = __ldg(&((const float4*)(g_gateT + (size_t)bc * W_))[w4]);

    const size_t base = (size_t)bc * (H_ * W_) + (size_t)q * HCH_A * W_;
    const float4* __restrict__ xp = (const float4*)(x + base);
    float4*       __restrict__ op = (float4*)(out + base);

#pragma unroll
    for (int half = 0; half < 2; ++half) {
        float4 v[8];
#pragma unroll
        for (int k = 0; k < 8; ++k)
            v[k] = __ldcs(&xp[(size_t)(hs + 4 * (half * 8 + k)) * (W_ / 4) + w4]);
#pragma unroll
        for (int k = 0; k < 8; ++k) {
            v[k].x *= gv.x; v[k].y *= gv.y; v[k].z *= gv.z; v[k].w *= gv.w;
            __stcs(&op[(size_t)(hs + 4 * (half * 8 + k)) * (W_ / 4) + w4], v[k]);
        }
    }
}

extern "C" void kernel_launch(void* const* d_in, const int* in_sizes, int n_in,
                              void* d_out, int out_size) {
    const float* x     = (const float*)d_in[0];
    const float* w_sub = (const float*)d_in[1];
    const float* b_sub = (const float*)d_in[2];
    const float* w_up  = (const float*)d_in[3];
    const float* b_up  = (const float*)d_in[4];
    const float* mb    = (const float*)d_in[5];
    const float* mu    = (const float*)d_in[6];
    float* out = (float*)d_out;

    reduce_h_partial_kernel<<<RBLK_, 256>>>(x);

    cudaLaunchAttribute attr[1];
    attr[0].id = cudaLaunchAttributeProgrammaticStreamSerialization;
    attr[0].val.programmaticStreamSerializationAllowed = 1;

    {
        cudaLaunchConfig_t cfg = {};
        cfg.gridDim  = dim3(256, 1, 1);
        cfg.blockDim = dim3(256, 1, 1);
        cfg.attrs    = attr;
        cfg.numAttrs = 1;
        cudaLaunchKernelEx(&cfg, gate_kernel, w_sub, b_sub, w_up, b_up, mb, mu);
    }
    {
        cudaLaunchConfig_t cfg = {};
        cfg.gridDim  = dim3(ABLK_, 1, 1);
        cfg.blockDim = dim3(256, 1, 1);
        cfg.attrs    = attr;
        cfg.numAttrs = 1;
        cudaLaunchKernelEx(&cfg, apply_gate_kernel, x, out);
    }
}